// round 16
// baseline (speedup 1.0000x reference)
#include <cuda_runtime.h>
#include <cuda_fp16.h>
#include <cstdint>
#include <math.h>

// Problem constants
#define BB   2
#define SS   2048
#define DD   1024
#define HH   16
#define DKK  64
#define DFFF 4096
#define MM   (BB * SS)          // 4096 rows
#define EPSF 1.1920929e-07f

// ---------------------------------------------------------------------------
// Scratch (device globals — no cudaMalloc allowed)
// ---------------------------------------------------------------------------
__device__ __half g_h  [MM * DD];    // rmsnorm1 out
__device__ __half g_q  [MM * DD];    // q (half, post-RoPE pre-scaled by 1/8)
__device__ __half g_k  [MM * DD];    // k (half, post-RoPE)
__device__ __half g_v  [MM * DD];    // v (half)
__device__ __half g_o  [MM * DD];    // attention out
__device__ float  g_x2 [MM * DD];
__device__ __half g_h2 [MM * DD];    // rmsnorm2 out
__device__ __half g_ff [MM * DFFF];  // relu FFN mid
// fp16 pair-packed weights: [K/2][N] of half2 (low = even-k)
__device__ uint32_t g_pwq[DD * DD / 2];
__device__ uint32_t g_pwk[DD * DD / 2];
__device__ uint32_t g_pwv[DD * DD / 2];
__device__ uint32_t g_pwo[DD * DD / 2];
__device__ uint32_t g_pw1[DD * DFFF / 2];
__device__ uint32_t g_pw2[DFFF * DD / 2];

// ---------------------------------------------------------------------------
// helpers
// ---------------------------------------------------------------------------
__device__ __forceinline__ uint32_t smem_u32(const void* p) {
    uint32_t a;
    asm("{ .reg .u64 t; cvta.to.shared.u64 t, %1; cvt.u32.u64 %0, t; }"
        : "=r"(a) : "l"(p));
    return a;
}
__device__ __forceinline__ void cp16(uint32_t saddr, const void* g) {
    asm volatile("cp.async.cg.shared.global [%0], [%1], 16;" :: "r"(saddr), "l"(g));
}
__device__ __forceinline__ void mma_f16(
    float* c, const uint32_t* a, const uint32_t* b)
{
    asm volatile(
        "mma.sync.aligned.m16n8k16.row.col.f32.f16.f16.f32 "
        "{%0,%1,%2,%3}, {%4,%5,%6,%7}, {%8,%9}, {%0,%1,%2,%3};"
        : "+f"(c[0]), "+f"(c[1]), "+f"(c[2]), "+f"(c[3])
        : "r"(a[0]), "r"(a[1]), "r"(a[2]), "r"(a[3]), "r"(b[0]), "r"(b[1]));
}
__device__ __forceinline__ uint32_t h2_bits(__half2 h) {
    return *reinterpret_cast<uint32_t*>(&h);
}
#define LDSM_X4(r0, r1, r2, r3, addr)                                         \
    asm volatile("ldmatrix.sync.aligned.m8n8.x4.shared.b16 "                  \
        "{%0,%1,%2,%3}, [%4];"                                                \
        : "=r"(r0), "=r"(r1), "=r"(r2), "=r"(r3) : "r"(addr))
#define LDSM_X4T(r0, r1, r2, r3, addr)                                        \
    asm volatile("ldmatrix.sync.aligned.m8n8.x4.trans.shared.b16 "            \
        "{%0,%1,%2,%3}, [%4];"                                                \
        : "=r"(r0), "=r"(r1), "=r"(r2), "=r"(r3) : "r"(addr))

// ---------------------------------------------------------------------------
// Fused weight pack: all 6 weights fp32 [K][N] -> half2 [K/2][N] in 1 launch
// ---------------------------------------------------------------------------
#define SEGW  (DD * DD / 2)          // 524288  (wq,wk,wv,wo)
#define SEGWF (DD * DFFF / 2)        // 2097152 (w1, w2)
#define PACK_TOTAL (4 * SEGW + 2 * SEGWF)
#define PACK_BLOCKS (PACK_TOTAL / 256)

__global__ void __launch_bounds__(256) pack_all_kernel(
    const float* __restrict__ s0, const float* __restrict__ s1,
    const float* __restrict__ s2, const float* __restrict__ s3,
    const float* __restrict__ s4, const float* __restrict__ s5,
    uint32_t* __restrict__ d0, uint32_t* __restrict__ d1,
    uint32_t* __restrict__ d2, uint32_t* __restrict__ d3,
    uint32_t* __restrict__ d4, uint32_t* __restrict__ d5)
{
    long long i = (long long)blockIdx.x * 256 + threadIdx.x;
    const float* src; uint32_t* dst; long long off; int N;
    if      (i < 1 * SEGW) { src = s0; dst = d0; off = i;            N = DD; }
    else if (i < 2 * SEGW) { src = s1; dst = d1; off = i - 1 * SEGW; N = DD; }
    else if (i < 3 * SEGW) { src = s2; dst = d2; off = i - 2 * SEGW; N = DD; }
    else if (i < 4 * SEGW) { src = s3; dst = d3; off = i - 3 * SEGW; N = DD; }
    else if (i < 4 * SEGW + SEGWF)
                           { src = s4; dst = d4; off = i - 4 * SEGW; N = DFFF; }
    else                   { src = s5; dst = d5; off = i - 4 * SEGW - SEGWF; N = DD; }
    long long k2 = off / N;
    long long n  = off - k2 * N;
    float a = src[(size_t)(2 * k2)     * N + n];
    float b = src[(size_t)(2 * k2 + 1) * N + n];
    dst[off] = h2_bits(__floats2half2_rn(a, b));
}

// ---------------------------------------------------------------------------
// fp16 mma.sync GEMM: C = A[M,K] @ W[K,N] + bias (+relu/+res)
// A: [M][K] half. W: pair-packed half2 [K/2][N].
// CTA 128x128, BK=32, 256 threads (2x4 warps, 64x32 warp tile),
// R16: 5-stage cp.async pipeline, single barrier per kt, 2 CTAs/SM.
// A fragments via ldmatrix.x4.
// epi: 0=bias, 1=bias+relu, 2=bias+residual ; outm: 0=fp32, 2=half
// ---------------------------------------------------------------------------
#define BM 128
#define BN 128
#define BK 32
#define ASTRH 40
#define BNP 136
#define A_WORDS (BM * ASTRH / 2)
#define B_WORDS (16 * BNP)
#define STG_WORDS (A_WORDS + B_WORDS)
#define NSTG 5
#define GEMM_SMEM (NSTG * STG_WORDS * 4)   // 94720 bytes

__device__ __forceinline__ void gemm_core(
    const __half* __restrict__ A, const uint32_t* __restrict__ Bp,
    const float* __restrict__ bias, const float* __restrict__ res,
    void* __restrict__ C, int Nd, int Kd, int brow, int bcol,
    int epi, int outm, uint32_t* sm)
{
    const int tid  = threadIdx.x;
    const int lane = tid & 31;
    const int wid  = tid >> 5;
    const int warp_m = (wid >> 2) * 64;
    const int warp_n = (wid & 3) * 32;
    const int KT = Kd / BK;

    const int tg  = lane >> 2;
    const int tig = lane & 3;
    const int alm = lane >> 3;
    const int alr = lane & 7;
    const uint32_t afrag_row = (uint32_t)((alm & 1) * 8 + alr);
    const uint32_t afrag_kof = (uint32_t)((alm >> 1) * 8);

    float acc[4][4][4];
    #pragma unroll
    for (int i = 0; i < 4; i++)
        #pragma unroll
        for (int j = 0; j < 4; j++)
            #pragma unroll
            for (int r = 0; r < 4; r++) acc[i][j][r] = 0.f;

    #define COPY_STAGE(s, kt) do {                                             \
        __half*   sA = (__half*)(sm + (s) * STG_WORDS);                        \
        uint32_t* sB = sm + (s) * STG_WORDS + A_WORDS;                         \
        int k0 = (kt) * BK;                                                    \
        _Pragma("unroll")                                                      \
        for (int i = 0; i < 2; i++) {                                          \
            int e = tid + i * 256;                                             \
            int m = e >> 2, c8 = (e & 3) << 3;                                 \
            cp16(smem_u32(sA + m * ASTRH + c8),                                \
                 A + (size_t)(brow + m) * Kd + k0 + c8);                       \
        }                                                                      \
        _Pragma("unroll")                                                      \
        for (int i = 0; i < 2; i++) {                                          \
            int e = tid + i * 256;                                             \
            int r = e >> 5, c4 = (e & 31) << 2;                                \
            cp16(smem_u32(sB + r * BNP + c4),                                  \
                 Bp + ((size_t)(k0 >> 1) + r) * Nd + bcol + c4);               \
        }                                                                      \
        asm volatile("cp.async.commit_group;");                                \
    } while (0)

    // prologue: 4 stages in flight
    COPY_STAGE(0, 0);
    COPY_STAGE(1, 1);
    COPY_STAGE(2, 2);
    COPY_STAGE(3, 3);

    int sidx = 0;
    for (int kt = 0; kt < KT; kt++) {
        // At loop top, issued stages are <= kt+3. Wait until stage kt done:
        // allowed outstanding = min(3, KT-1-kt).
        int ahead = KT - 1 - kt;
        if (ahead >= 3)      asm volatile("cp.async.wait_group 3;");
        else if (ahead == 2) asm volatile("cp.async.wait_group 2;");
        else if (ahead == 1) asm volatile("cp.async.wait_group 1;");
        else                 asm volatile("cp.async.wait_group 0;");
        __syncthreads();

        // Buffer (sidx+4)%5 was last read in iteration kt-1; safe after barrier.
        if (kt + 4 < KT) {
            int s4 = sidx + 4; if (s4 >= NSTG) s4 -= NSTG;
            COPY_STAGE(s4, kt + 4);
        }

        const __half*   As = (const __half*)(sm + sidx * STG_WORDS);
        const uint32_t* Bs = sm + sidx * STG_WORDS + A_WORDS;

        uint32_t aBase = smem_u32(As + (warp_m + afrag_row) * ASTRH + afrag_kof);

        #pragma unroll
        for (int ks = 0; ks < 2; ks++) {
            uint32_t af[4][4], bf[4][2];
            #pragma unroll
            for (int mi = 0; mi < 4; mi++)
                LDSM_X4(af[mi][0], af[mi][1], af[mi][2], af[mi][3],
                        aBase + (uint32_t)(mi * 16 * ASTRH + ks * 16) * 2);
            #pragma unroll
            for (int ni = 0; ni < 4; ni++) {
                int cn = warp_n + ni * 8 + tg;
                bf[ni][0] = Bs[(ks * 8 + tig    ) * BNP + cn];
                bf[ni][1] = Bs[(ks * 8 + tig + 4) * BNP + cn];
            }
            #pragma unroll
            for (int mi = 0; mi < 4; mi++)
                #pragma unroll
                for (int ni = 0; ni < 4; ni++)
                    mma_f16(acc[mi][ni], af[mi], bf[ni]);
        }
        if (++sidx == NSTG) sidx = 0;
    }

    #pragma unroll
    for (int mi = 0; mi < 4; mi++) {
        int row0 = brow + warp_m + mi * 16 + tg;
        #pragma unroll
        for (int ni = 0; ni < 4; ni++) {
            int col = bcol + warp_n + ni * 8 + tig * 2;
            float2 bv = *(const float2*)(bias + col);
            #pragma unroll
            for (int half_ = 0; half_ < 2; half_++) {
                int row = row0 + half_ * 8;
                float v0 = acc[mi][ni][half_ * 2 + 0] + bv.x;
                float v1 = acc[mi][ni][half_ * 2 + 1] + bv.y;
                if (epi == 1) { v0 = fmaxf(v0, 0.f); v1 = fmaxf(v1, 0.f); }
                if (epi == 2) {
                    float2 rv = *(const float2*)(res + (size_t)row * Nd + col);
                    v0 += rv.x; v1 += rv.y;
                }
                if (outm == 2) {
                    *(__half2*)((__half*)C + (size_t)row * Nd + col) =
                        __floats2half2_rn(v0, v1);
                } else {
                    float2 o2; o2.x = v0; o2.y = v1;
                    *(float2*)((float*)C + (size_t)row * Nd + col) = o2;
                }
            }
        }
    }
    #undef COPY_STAGE
}

__global__ void __launch_bounds__(256, 2) gemm_h(
    const __half* __restrict__ A, const uint32_t* __restrict__ Bp,
    const float* __restrict__ bias, const float* __restrict__ res,
    void* __restrict__ C, int Nd, int Kd, int epi, int outm)
{
    extern __shared__ uint32_t sm[];
    gemm_core(A, Bp, bias, res, C, Nd, Kd,
              blockIdx.y * BM, blockIdx.x * BN, epi, outm, sm);
}

// Fused QKV: grid.x in [0,24); nsel = x>>3. All outputs half.
__global__ void __launch_bounds__(256, 2) gemm_qkv(
    const __half* __restrict__ A,
    const uint32_t* __restrict__ Bq, const uint32_t* __restrict__ Bk,
    const uint32_t* __restrict__ Bv,
    const float* __restrict__ bq, const float* __restrict__ bk,
    const float* __restrict__ bv,
    __half* __restrict__ Cq, __half* __restrict__ Ck, __half* __restrict__ Cv)
{
    extern __shared__ uint32_t sm[];
    int nsel = blockIdx.x >> 3;
    int bcol = (blockIdx.x & 7) * BN;
    const uint32_t* B = (nsel == 0) ? Bq : (nsel == 1) ? Bk : Bv;
    const float* bi   = (nsel == 0) ? bq : (nsel == 1) ? bk : bv;
    __half* C         = (nsel == 0) ? Cq : (nsel == 1) ? Ck : Cv;
    gemm_core(A, B, bi, nullptr, C, DD, DD,
              blockIdx.y * BM, bcol, 0, 2, sm);
}

// ---------------------------------------------------------------------------
// RMSNorm: fp32 in, half out
// ---------------------------------------------------------------------------
__global__ void __launch_bounds__(256) rmsnorm_h_kernel(
    const float* __restrict__ x, const float* __restrict__ g,
    __half* __restrict__ out)
{
    int row = blockIdx.x;
    const float4* xr = (const float4*)(x + (size_t)row * DD);
    float4 xv = xr[threadIdx.x];
    float ss = xv.x * xv.x + xv.y * xv.y + xv.z * xv.z + xv.w * xv.w;
    #pragma unroll
    for (int off = 16; off > 0; off >>= 1)
        ss += __shfl_xor_sync(0xFFFFFFFFu, ss, off);
    __shared__ float sred[8];
    __shared__ float sscale;
    int warp = threadIdx.x >> 5;
    if ((threadIdx.x & 31) == 0) sred[warp] = ss;
    __syncthreads();
    if (threadIdx.x == 0) {
        float t = 0.f;
        #pragma unroll
        for (int i = 0; i < 8; i++) t += sred[i];
        sscale = rsqrtf(t / (float)DD + EPSF);
    }
    __syncthreads();
    float sc = sscale;
    float4 gv = ((const float4*)g)[threadIdx.x];
    uint2 u;
    u.x = h2_bits(__floats2half2_rn(xv.x * sc * gv.x, xv.y * sc * gv.y));
    u.y = h2_bits(__floats2half2_rn(xv.z * sc * gv.z, xv.w * sc * gv.w));
    ((uint2*)(out + (size_t)row * DD))[threadIdx.x] = u;
}

// ---------------------------------------------------------------------------
// RoPE on half q,k — half2 vectorized; q scaled by 1/sqrt(dk)=0.125
// ---------------------------------------------------------------------------
#define LOG2_10000_OVER_32 0.41524101186092029f
__global__ void rope_kernel(__half* __restrict__ q, __half* __restrict__ k)
{
    int idx = blockIdx.x * blockDim.x + threadIdx.x;   // < MM*HH*16
    int j2  = idx & 15;
    int h   = (idx >> 4) & (HH - 1);
    int row = idx >> 8;
    int s   = row & (SS - 1);
    int j   = 2 * j2;

    float if0 = exp2f(-(float)j       * LOG2_10000_OVER_32);
    float if1 = exp2f(-(float)(j + 1) * LOG2_10000_OVER_32);
    float sn0, cs0, sn1, cs1;
    sincosf((float)s * if0, &sn0, &cs0);
    sincosf((float)s * if1, &sn1, &cs1);

    size_t base = (size_t)row * DD + h * DKK + j;

    {
        __half2 a = *(__half2*)(q + base);
        __half2 b = *(__half2*)(q + base + 32);
        float a0 = __half2float(a.x), a1 = __half2float(a.y);
        float b0 = __half2float(b.x), b1 = __half2float(b.y);
        *(__half2*)(q + base) = __floats2half2_rn(
            (a0 * cs0 - b0 * sn0) * 0.125f, (a1 * cs1 - b1 * sn1) * 0.125f);
        *(__half2*)(q + base + 32) = __floats2half2_rn(
            (b0 * cs0 + a0 * sn0) * 0.125f, (b1 * cs1 + a1 * sn1) * 0.125f);
    }
    {
        __half2 a = *(__half2*)(k + base);
        __half2 b = *(__half2*)(k + base + 32);
        float a0 = __half2float(a.x), a1 = __half2float(a.y);
        float b0 = __half2float(b.x), b1 = __half2float(b.y);
        *(__half2*)(k + base) = __floats2half2_rn(
            a0 * cs0 - b0 * sn0, a1 * cs1 - b1 * sn1);
        *(__half2*)(k + base + 32) = __floats2half2_rn(
            b0 * cs0 + a0 * sn0, b1 * cs1 + a1 * sn1);
    }
}

// ---------------------------------------------------------------------------
// Flash attention, fp16 m16n8k16 — R11/R13 config; R16: QK^T K-fragments
// via non-trans ldmatrix.x4 (keys are rows in K-major smem).
// ---------------------------------------------------------------------------
#define KSH 72
#define VSH 72
#define PSH 72
#define AOFF_K0 0
#define AOFF_K1 (64 * KSH)
#define AOFF_V0 (2 * 64 * KSH)
#define AOFF_V1 (2 * 64 * KSH + 64 * VSH)
#define AOFF_P  (2 * 64 * KSH + 2 * 64 * VSH)
#define ATTN_SMEM ((2 * 64 * KSH + 2 * 64 * VSH + 64 * PSH) * 2)

__global__ void __launch_bounds__(128, 3) attn_mma(
    const __half* __restrict__ q, const __half* __restrict__ k,
    const __half* __restrict__ v, __half* __restrict__ o)
{
    extern __shared__ __half smh[];
    __half* Ks[2] = { smh + AOFF_K0, smh + AOFF_K1 };
    __half* Vs[2] = { smh + AOFF_V0, smh + AOFF_V1 };
    __half* Ps    = smh + AOFF_P;

    const int tid  = threadIdx.x;
    const int lane = tid & 31;
    const int wid  = tid >> 5;
    const int wm   = wid * 16;
    const int tg   = lane >> 2;
    const int tig  = lane & 3;
    const int lm = lane >> 3;
    const int lr = lane & 7;
    // V fragments (trans): matrix lm covers key (lm&1)*8, dk (lm>>1)*8
    const uint32_t vfrag_off =
        (uint32_t)(((lm & 1) * 8 + lr) * VSH + (lm >> 1) * 8) * 2;
    // K fragments (non-trans): matrix lm covers key (lm&1)*8, k (lm>>1)*8
    const uint32_t kfrag_off =
        (uint32_t)(((lm & 1) * 8 + lr) * KSH + (lm >> 1) * 8) * 2;

    const int h  = blockIdx.y;
    const int b  = blockIdx.z;
    const int q0 = blockIdx.x * 64;
    const size_t hb = (size_t)h * DKK;

    uint32_t qf[4][4];
    {
        size_t r0 = ((size_t)(b * SS + q0 + wm + tg)) * DD + hb;
        size_t r8 = r0 + (size_t)8 * DD;
        #pragma unroll
        for (int ks = 0; ks < 4; ks++) {
            int c = ks * 16 + 2 * tig;
            qf[ks][0] = *(const uint32_t*)(q + r0 + c);
            qf[ks][1] = *(const uint32_t*)(q + r8 + c);
            qf[ks][2] = *(const uint32_t*)(q + r0 + c + 8);
            qf[ks][3] = *(const uint32_t*)(q + r8 + c + 8);
        }
    }

    float oacc[8][4];
    #pragma unroll
    for (int ni = 0; ni < 8; ni++)
        #pragma unroll
        for (int r = 0; r < 4; r++) oacc[ni][r] = 0.f;
    float m0 = -1e30f, m1 = -1e30f, l0 = 0.f, l1 = 0.f;

    const size_t kvbase = ((size_t)(b * SS)) * DD + hb;

    #define KV_PREFETCH(bf, kt) do {                                          \
        const __half* kg = k + kvbase + (size_t)((kt) * 64) * DD;             \
        const __half* vg = v + kvbase + (size_t)((kt) * 64) * DD;             \
        uint32_t kb = smem_u32(Ks[bf]);                                       \
        uint32_t vb = smem_u32(Vs[bf]);                                       \
        _Pragma("unroll")                                                     \
        for (int i = 0; i < 4; i++) {                                         \
            int e = tid + i * 128;                                            \
            int row = e >> 3, c = e & 7;                                      \
            cp16(kb + (row * KSH + c * 8) * 2, kg + (size_t)row * DD + c * 8);\
            cp16(vb + (row * VSH + c * 8) * 2, vg + (size_t)row * DD + c * 8);\
        }                                                                     \
        asm volatile("cp.async.commit_group;");                               \
    } while (0)

    KV_PREFETCH(0, 0);

    const int NT = SS / 64;
    for (int kt = 0; kt < NT; kt++) {
        int cur = kt & 1;
        asm volatile("cp.async.wait_group 0;");
        __syncthreads();
        if (kt + 1 < NT) KV_PREFETCH(cur ^ 1, kt + 1);

        // ---- S = Q @ K^T (K fragments via ldmatrix.x4) ----
        float sacc[8][4];
        #pragma unroll
        for (int ni = 0; ni < 8; ni++)
            #pragma unroll
            for (int r = 0; r < 4; r++) sacc[ni][r] = 0.f;

        uint32_t kmBase = smem_u32(Ks[cur]) + kfrag_off;
        #pragma unroll
        for (int ks = 0; ks < 4; ks++) {
            #pragma unroll
            for (int g = 0; g < 4; g++) {        // 16-key group
                uint32_t r0, r1, r2, r3;
                LDSM_X4(r0, r1, r2, r3,
                        kmBase + (uint32_t)(g * 16 * KSH + ks * 16) * 2);
                uint32_t bA[2] = { r0, r2 };
                uint32_t bB[2] = { r1, r3 };
                mma_f16(sacc[2 * g    ], qf[ks], bA);
                mma_f16(sacc[2 * g + 1], qf[ks], bB);
            }
        }

        // ---- online softmax ----
        float rmax0 = -1e30f, rmax1 = -1e30f;
        #pragma unroll
        for (int ni = 0; ni < 8; ni++) {
            rmax0 = fmaxf(rmax0, fmaxf(sacc[ni][0], sacc[ni][1]));
            rmax1 = fmaxf(rmax1, fmaxf(sacc[ni][2], sacc[ni][3]));
        }
        #pragma unroll
        for (int d = 1; d < 4; d <<= 1) {
            rmax0 = fmaxf(rmax0, __shfl_xor_sync(0xFFFFFFFFu, rmax0, d));
            rmax1 = fmaxf(rmax1, __shfl_xor_sync(0xFFFFFFFFu, rmax1, d));
        }
        float nm0 = fmaxf(m0, rmax0);
        float nm1 = fmaxf(m1, rmax1);
        float corr0 = __expf(m0 - nm0);
        float corr1 = __expf(m1 - nm1);

        float rsum0 = 0.f, rsum1 = 0.f;
        #pragma unroll
        for (int ni = 0; ni < 8; ni++) {
            float p0 = __expf(sacc[ni][0] - nm0);
            float p1 = __expf(sacc[ni][1] - nm0);
            float p2 = __expf(sacc[ni][2] - nm1);
            float p3 = __expf(sacc[ni][3] - nm1);
            rsum0 += p0 + p1;
            rsum1 += p2 + p3;
            *(__half2*)(Ps + (wm + tg    ) * PSH + ni * 8 + 2 * tig) =
                __floats2half2_rn(p0, p1);
            *(__half2*)(Ps + (wm + tg + 8) * PSH + ni * 8 + 2 * tig) =
                __floats2half2_rn(p2, p3);
        }
        #pragma unroll
        for (int d = 1; d < 4; d <<= 1) {
            rsum0 += __shfl_xor_sync(0xFFFFFFFFu, rsum0, d);
            rsum1 += __shfl_xor_sync(0xFFFFFFFFu, rsum1, d);
        }
        l0 = l0 * corr0 + rsum0;
        l1 = l1 * corr1 + rsum1;
        m0 = nm0; m1 = nm1;

        #pragma unroll
        for (int ni = 0; ni < 8; ni++) {
            oacc[ni][0] *= corr0; oacc[ni][1] *= corr0;
            oacc[ni][2] *= corr1; oacc[ni][3] *= corr1;
        }

        __syncwarp();

        // ---- O += P @ V ----
        uint32_t vmBase = smem_u32(Vs[cur]) + vfrag_off;
        #pragma unroll
        for (int ks = 0; ks < 4; ks++) {
            uint32_t af[4];
            const __half* pr = Ps + (wm + tg) * PSH + ks * 16 + 2 * tig;
            af[0] = *(const uint32_t*)(pr);
            af[1] = *(const uint32_t*)(pr + 8 * PSH);
            af[2] = *(const uint32_t*)(pr + 8);
            af[3] = *(const uint32_t*)(pr + 8 * PSH + 8);
            #pragma unroll
            for (int nip = 0; nip < 4; nip++) {
                uint32_t b0a, b1a, b0b, b1b;
                LDSM_X4T(b0a, b1a, b0b, b1b,
                         vmBase + (uint32_t)(ks * 16 * VSH + nip * 16) * 2);
                uint32_t bA[2] = { b0a, b1a };
                uint32_t bB[2] = { b0b, b1b };
                mma_f16(oacc[2 * nip    ], af, bA);
                mma_f16(oacc[2 * nip + 1], af, bB);
            }
        }
        __syncwarp();
    }

    float inv0 = 1.f / l0;
    float inv1 = 1.f / l1;
    size_t r0 = ((size_t)(b * SS + q0 + wm + tg)) * DD + hb;
    size_t r8 = r0 + (size_t)8 * DD;
    #pragma unroll
    for (int ni = 0; ni < 8; ni++) {
        int c = ni * 8 + 2 * tig;
        *(__half2*)(o + r0 + c) =
            __floats2half2_rn(oacc[ni][0] * inv0, oacc[ni][1] * inv0);
        *(__half2*)(o + r8 + c) =
            __floats2half2_rn(oacc[ni][2] * inv1, oacc[ni][3] * inv1);
    }
    #undef KV_PREFETCH
}

// ---------------------------------------------------------------------------
// Host orchestration
// ---------------------------------------------------------------------------
extern "C" void kernel_launch(void* const* d_in, const int* in_sizes, int n_in,
                              void* d_out, int out_size)
{
    (void)in_sizes; (void)n_in; (void)out_size;

    const float* x  = (const float*)d_in[0];
    const float* wq = (const float*)d_in[1];
    const float* bq = (const float*)d_in[2];
    const float* wk = (const float*)d_in[3];
    const float* bk = (const float*)d_in[4];
    const float* wv = (const float*)d_in[5];
    const float* bv = (const float*)d_in[6];
    const float* wo = (const float*)d_in[7];
    const float* bo = (const float*)d_in[8];
    const float* w1 = (const float*)d_in[9];
    const float* b1 = (const float*)d_in[10];
    const float* w2 = (const float*)d_in[11];
    const float* b2 = (const float*)d_in[12];
    const float* g1 = (const float*)d_in[13];
    const float* g2 = (const float*)d_in[14];
    float* out = (float*)d_out;

    __half *ph, *pq, *pk, *pv, *po, *ph2, *pff;
    float  *px2;
    uint32_t *ppwq, *ppwk, *ppwv, *ppwo, *ppw1, *ppw2;
    cudaGetSymbolAddress((void**)&ph,  g_h);
    cudaGetSymbolAddress((void**)&pq,  g_q);
    cudaGetSymbolAddress((void**)&pk,  g_k);
    cudaGetSymbolAddress((void**)&pv,  g_v);
    cudaGetSymbolAddress((void**)&po,  g_o);
    cudaGetSymbolAddress((void**)&px2, g_x2);
    cudaGetSymbolAddress((void**)&ph2, g_h2);
    cudaGetSymbolAddress((void**)&pff, g_ff);
    cudaGetSymbolAddress((void**)&ppwq, g_pwq);
    cudaGetSymbolAddress((void**)&ppwk, g_pwk);
    cudaGetSymbolAddress((void**)&ppwv, g_pwv);
    cudaGetSymbolAddress((void**)&ppwo, g_pwo);
    cudaGetSymbolAddress((void**)&ppw1, g_pw1);
    cudaGetSymbolAddress((void**)&ppw2, g_pw2);

    cudaFuncSetAttribute(attn_mma,
        cudaFuncAttributeMaxDynamicSharedMemorySize, ATTN_SMEM);
    cudaFuncSetAttribute(gemm_h,
        cudaFuncAttributeMaxDynamicSharedMemorySize, GEMM_SMEM);
    cudaFuncSetAttribute(gemm_qkv,
        cudaFuncAttributeMaxDynamicSharedMemorySize, GEMM_SMEM);

    dim3 gD(DD / BN,   MM / BM);   // (8, 32)
    dim3 gF(DFFF / BN, MM / BM);   // (32, 32)

    // 1) pack all weights in one launch
    pack_all_kernel<<<PACK_BLOCKS, 256>>>(
        wq, wk, wv, wo, w1, w2, ppwq, ppwk, ppwv, ppwo, ppw1, ppw2);

    // 2) h = rmsnorm(x, g1) -> half
    rmsnorm_h_kernel<<<MM, 256>>>(x, g1, ph);

    // 3) fused QKV projections -> half q,k,v
    gemm_qkv<<<dim3(24, MM / BM), 256, GEMM_SMEM>>>(
        ph, ppwq, ppwk, ppwv, bq, bk, bv, pq, pk, pv);

    // 4) RoPE on half q,k
    rope_kernel<<<(MM * HH * 16) / 256, 256>>>(pq, pk);

    // 5) attention (fp16, 64-query CTAs, 3 CTA/SM) -> o half
    attn_mma<<<dim3(SS / 64, HH, BB), 128, ATTN_SMEM>>>(pq, pk, pv, po);

    // 6) x2 = x + o @ wo + bo   (fp32 out)
    gemm_h<<<gD, 256, GEMM_SMEM>>>(po, ppwo, bo, x, px2, DD, DD, 2, 0);

    // 7) h2 = rmsnorm(x2, g2) -> half
    rmsnorm_h_kernel<<<MM, 256>>>(px2, g2, ph2);

    // 8) ff = relu(h2 @ w1 + b1) -> half
    gemm_h<<<gF, 256, GEMM_SMEM>>>(ph2, ppw1, b1, nullptr, pff, DFFF, DD, 1, 2);

    // 9) out = x2 + ff @ w2 + b2   (fp32 out)
    gemm_h<<<gD, 256, GEMM_SMEM>>>(pff, ppw2, b2, px2, out, DD, DFFF, 2, 0);
}

// round 17
// speedup vs baseline: 1.0460x; 1.0460x over previous
#include <cuda_runtime.h>
#include <cuda_fp16.h>
#include <cstdint>
#include <math.h>

// Problem constants
#define BB   2
#define SS   2048
#define DD   1024
#define HH   16
#define DKK  64
#define DFFF 4096
#define MM   (BB * SS)          // 4096 rows
#define EPSF 1.1920929e-07f

// ---------------------------------------------------------------------------
// Scratch (device globals — no cudaMalloc allowed)
// ---------------------------------------------------------------------------
__device__ __half g_h  [MM * DD];    // rmsnorm1 out
__device__ __half g_q  [MM * DD];    // q (half, post-RoPE pre-scaled by 1/8)
__device__ __half g_k  [MM * DD];    // k (half, post-RoPE)
__device__ __half g_v  [MM * DD];    // v (half)
__device__ __half g_o  [MM * DD];    // attention out
__device__ float  g_x2 [MM * DD];
__device__ __half g_h2 [MM * DD];    // rmsnorm2 out
__device__ __half g_ff [MM * DFFF];  // relu FFN mid
// fp16 pair-packed weights: [K/2][N] of half2 (low = even-k)
__device__ uint32_t g_pwq[DD * DD / 2];
__device__ uint32_t g_pwk[DD * DD / 2];
__device__ uint32_t g_pwv[DD * DD / 2];
__device__ uint32_t g_pwo[DD * DD / 2];
__device__ uint32_t g_pw1[DD * DFFF / 2];
__device__ uint32_t g_pw2[DFFF * DD / 2];

// ---------------------------------------------------------------------------
// helpers
// ---------------------------------------------------------------------------
__device__ __forceinline__ uint32_t smem_u32(const void* p) {
    uint32_t a;
    asm("{ .reg .u64 t; cvta.to.shared.u64 t, %1; cvt.u32.u64 %0, t; }"
        : "=r"(a) : "l"(p));
    return a;
}
__device__ __forceinline__ void cp16(uint32_t saddr, const void* g) {
    asm volatile("cp.async.cg.shared.global [%0], [%1], 16;" :: "r"(saddr), "l"(g));
}
__device__ __forceinline__ void mma_f16(
    float* c, const uint32_t* a, const uint32_t* b)
{
    asm volatile(
        "mma.sync.aligned.m16n8k16.row.col.f32.f16.f16.f32 "
        "{%0,%1,%2,%3}, {%4,%5,%6,%7}, {%8,%9}, {%0,%1,%2,%3};"
        : "+f"(c[0]), "+f"(c[1]), "+f"(c[2]), "+f"(c[3])
        : "r"(a[0]), "r"(a[1]), "r"(a[2]), "r"(a[3]), "r"(b[0]), "r"(b[1]));
}
__device__ __forceinline__ uint32_t h2_bits(__half2 h) {
    return *reinterpret_cast<uint32_t*>(&h);
}
#define LDSM_X4(r0, r1, r2, r3, addr)                                         \
    asm volatile("ldmatrix.sync.aligned.m8n8.x4.shared.b16 "                  \
        "{%0,%1,%2,%3}, [%4];"                                                \
        : "=r"(r0), "=r"(r1), "=r"(r2), "=r"(r3) : "r"(addr))
#define LDSM_X4T(r0, r1, r2, r3, addr)                                        \
    asm volatile("ldmatrix.sync.aligned.m8n8.x4.trans.shared.b16 "            \
        "{%0,%1,%2,%3}, [%4];"                                                \
        : "=r"(r0), "=r"(r1), "=r"(r2), "=r"(r3) : "r"(addr))

// ---------------------------------------------------------------------------
// Fused weight pack: all 6 weights fp32 [K][N] -> half2 [K/2][N] in 1 launch
// ---------------------------------------------------------------------------
#define SEGW  (DD * DD / 2)          // 524288  (wq,wk,wv,wo)
#define SEGWF (DD * DFFF / 2)        // 2097152 (w1, w2)
#define PACK_TOTAL (4 * SEGW + 2 * SEGWF)
#define PACK_BLOCKS (PACK_TOTAL / 256)

__global__ void __launch_bounds__(256) pack_all_kernel(
    const float* __restrict__ s0, const float* __restrict__ s1,
    const float* __restrict__ s2, const float* __restrict__ s3,
    const float* __restrict__ s4, const float* __restrict__ s5,
    uint32_t* __restrict__ d0, uint32_t* __restrict__ d1,
    uint32_t* __restrict__ d2, uint32_t* __restrict__ d3,
    uint32_t* __restrict__ d4, uint32_t* __restrict__ d5)
{
    long long i = (long long)blockIdx.x * 256 + threadIdx.x;
    const float* src; uint32_t* dst; long long off; int N;
    if      (i < 1 * SEGW) { src = s0; dst = d0; off = i;            N = DD; }
    else if (i < 2 * SEGW) { src = s1; dst = d1; off = i - 1 * SEGW; N = DD; }
    else if (i < 3 * SEGW) { src = s2; dst = d2; off = i - 2 * SEGW; N = DD; }
    else if (i < 4 * SEGW) { src = s3; dst = d3; off = i - 3 * SEGW; N = DD; }
    else if (i < 4 * SEGW + SEGWF)
                           { src = s4; dst = d4; off = i - 4 * SEGW; N = DFFF; }
    else                   { src = s5; dst = d5; off = i - 4 * SEGW - SEGWF; N = DD; }
    long long k2 = off / N;
    long long n  = off - k2 * N;
    float a = src[(size_t)(2 * k2)     * N + n];
    float b = src[(size_t)(2 * k2 + 1) * N + n];
    dst[off] = h2_bits(__floats2half2_rn(a, b));
}

// ---------------------------------------------------------------------------
// fp16 mma.sync GEMM — exact R15 configuration (proven 555.4us).
// C = A[M,K] @ W[K,N] + bias (+relu/+res)
// A: [M][K] half. W: pair-packed half2 [K/2][N].
// CTA 128x128, BK=32, 256 threads (2x4 warps, 64x32 warp tile),
// 4-stage cp.async pipeline, single barrier per kt, 2 CTAs/SM.
// A fragments via ldmatrix.x4.
// epi: 0=bias, 1=bias+relu, 2=bias+residual ; outm: 0=fp32, 2=half
// ---------------------------------------------------------------------------
#define BM 128
#define BN 128
#define BK 32
#define ASTRH 40
#define BNP 136
#define A_WORDS (BM * ASTRH / 2)
#define B_WORDS (16 * BNP)
#define STG_WORDS (A_WORDS + B_WORDS)
#define NSTG 4
#define GEMM_SMEM (NSTG * STG_WORDS * 4)   // 75776 bytes

__device__ __forceinline__ void gemm_core(
    const __half* __restrict__ A, const uint32_t* __restrict__ Bp,
    const float* __restrict__ bias, const float* __restrict__ res,
    void* __restrict__ C, int Nd, int Kd, int brow, int bcol,
    int epi, int outm, uint32_t* sm)
{
    const int tid  = threadIdx.x;
    const int lane = tid & 31;
    const int wid  = tid >> 5;
    const int warp_m = (wid >> 2) * 64;
    const int warp_n = (wid & 3) * 32;
    const int KT = Kd / BK;

    const int tg  = lane >> 2;
    const int tig = lane & 3;
    const int alm = lane >> 3;
    const int alr = lane & 7;
    const uint32_t afrag_row = (uint32_t)((alm & 1) * 8 + alr);
    const uint32_t afrag_kof = (uint32_t)((alm >> 1) * 8);

    float acc[4][4][4];
    #pragma unroll
    for (int i = 0; i < 4; i++)
        #pragma unroll
        for (int j = 0; j < 4; j++)
            #pragma unroll
            for (int r = 0; r < 4; r++) acc[i][j][r] = 0.f;

    #define COPY_STAGE(s, kt) do {                                             \
        __half*   sA = (__half*)(sm + (s) * STG_WORDS);                        \
        uint32_t* sB = sm + (s) * STG_WORDS + A_WORDS;                         \
        int k0 = (kt) * BK;                                                    \
        _Pragma("unroll")                                                      \
        for (int i = 0; i < 2; i++) {                                          \
            int e = tid + i * 256;                                             \
            int m = e >> 2, c8 = (e & 3) << 3;                                 \
            cp16(smem_u32(sA + m * ASTRH + c8),                                \
                 A + (size_t)(brow + m) * Kd + k0 + c8);                       \
        }                                                                      \
        _Pragma("unroll")                                                      \
        for (int i = 0; i < 2; i++) {                                          \
            int e = tid + i * 256;                                             \
            int r = e >> 5, c4 = (e & 31) << 2;                                \
            cp16(smem_u32(sB + r * BNP + c4),                                  \
                 Bp + ((size_t)(k0 >> 1) + r) * Nd + bcol + c4);               \
        }                                                                      \
        asm volatile("cp.async.commit_group;");                                \
    } while (0)

    COPY_STAGE(0, 0);
    COPY_STAGE(1, 1);
    COPY_STAGE(2, 2);

    for (int kt = 0; kt < KT; kt++) {
        int s = kt & (NSTG - 1);

        int ahead = KT - 1 - kt;
        if (ahead >= 2)      asm volatile("cp.async.wait_group 2;");
        else if (ahead == 1) asm volatile("cp.async.wait_group 1;");
        else                 asm volatile("cp.async.wait_group 0;");
        __syncthreads();

        if (kt + 3 < KT) COPY_STAGE((kt + 3) & (NSTG - 1), kt + 3);

        const __half*   As = (const __half*)(sm + s * STG_WORDS);
        const uint32_t* Bs = sm + s * STG_WORDS + A_WORDS;

        uint32_t aBase = smem_u32(As + (warp_m + afrag_row) * ASTRH + afrag_kof);

        #pragma unroll
        for (int ks = 0; ks < 2; ks++) {
            uint32_t af[4][4], bf[4][2];
            #pragma unroll
            for (int mi = 0; mi < 4; mi++)
                LDSM_X4(af[mi][0], af[mi][1], af[mi][2], af[mi][3],
                        aBase + (uint32_t)(mi * 16 * ASTRH + ks * 16) * 2);
            #pragma unroll
            for (int ni = 0; ni < 4; ni++) {
                int cn = warp_n + ni * 8 + tg;
                bf[ni][0] = Bs[(ks * 8 + tig    ) * BNP + cn];
                bf[ni][1] = Bs[(ks * 8 + tig + 4) * BNP + cn];
            }
            #pragma unroll
            for (int mi = 0; mi < 4; mi++)
                #pragma unroll
                for (int ni = 0; ni < 4; ni++)
                    mma_f16(acc[mi][ni], af[mi], bf[ni]);
        }
        // no trailing sync
    }

    #pragma unroll
    for (int mi = 0; mi < 4; mi++) {
        int row0 = brow + warp_m + mi * 16 + tg;
        #pragma unroll
        for (int ni = 0; ni < 4; ni++) {
            int col = bcol + warp_n + ni * 8 + tig * 2;
            float2 bv = *(const float2*)(bias + col);
            #pragma unroll
            for (int half_ = 0; half_ < 2; half_++) {
                int row = row0 + half_ * 8;
                float v0 = acc[mi][ni][half_ * 2 + 0] + bv.x;
                float v1 = acc[mi][ni][half_ * 2 + 1] + bv.y;
                if (epi == 1) { v0 = fmaxf(v0, 0.f); v1 = fmaxf(v1, 0.f); }
                if (epi == 2) {
                    float2 rv = *(const float2*)(res + (size_t)row * Nd + col);
                    v0 += rv.x; v1 += rv.y;
                }
                if (outm == 2) {
                    *(__half2*)((__half*)C + (size_t)row * Nd + col) =
                        __floats2half2_rn(v0, v1);
                } else {
                    float2 o2; o2.x = v0; o2.y = v1;
                    *(float2*)((float*)C + (size_t)row * Nd + col) = o2;
                }
            }
        }
    }
    #undef COPY_STAGE
}

__global__ void __launch_bounds__(256, 2) gemm_h(
    const __half* __restrict__ A, const uint32_t* __restrict__ Bp,
    const float* __restrict__ bias, const float* __restrict__ res,
    void* __restrict__ C, int Nd, int Kd, int epi, int outm)
{
    extern __shared__ uint32_t sm[];
    gemm_core(A, Bp, bias, res, C, Nd, Kd,
              blockIdx.y * BM, blockIdx.x * BN, epi, outm, sm);
}

// Fused QKV: grid.x in [0,24); nsel = x>>3. All outputs half.
__global__ void __launch_bounds__(256, 2) gemm_qkv(
    const __half* __restrict__ A,
    const uint32_t* __restrict__ Bq, const uint32_t* __restrict__ Bk,
    const uint32_t* __restrict__ Bv,
    const float* __restrict__ bq, const float* __restrict__ bk,
    const float* __restrict__ bv,
    __half* __restrict__ Cq, __half* __restrict__ Ck, __half* __restrict__ Cv)
{
    extern __shared__ uint32_t sm[];
    int nsel = blockIdx.x >> 3;
    int bcol = (blockIdx.x & 7) * BN;
    const uint32_t* B = (nsel == 0) ? Bq : (nsel == 1) ? Bk : Bv;
    const float* bi   = (nsel == 0) ? bq : (nsel == 1) ? bk : bv;
    __half* C         = (nsel == 0) ? Cq : (nsel == 1) ? Ck : Cv;
    gemm_core(A, B, bi, nullptr, C, DD, DD,
              blockIdx.y * BM, bcol, 0, 2, sm);
}

// ---------------------------------------------------------------------------
// RMSNorm: fp32 in, half out
// ---------------------------------------------------------------------------
__global__ void __launch_bounds__(256) rmsnorm_h_kernel(
    const float* __restrict__ x, const float* __restrict__ g,
    __half* __restrict__ out)
{
    int row = blockIdx.x;
    const float4* xr = (const float4*)(x + (size_t)row * DD);
    float4 xv = xr[threadIdx.x];
    float ss = xv.x * xv.x + xv.y * xv.y + xv.z * xv.z + xv.w * xv.w;
    #pragma unroll
    for (int off = 16; off > 0; off >>= 1)
        ss += __shfl_xor_sync(0xFFFFFFFFu, ss, off);
    __shared__ float sred[8];
    __shared__ float sscale;
    int warp = threadIdx.x >> 5;
    if ((threadIdx.x & 31) == 0) sred[warp] = ss;
    __syncthreads();
    if (threadIdx.x == 0) {
        float t = 0.f;
        #pragma unroll
        for (int i = 0; i < 8; i++) t += sred[i];
        sscale = rsqrtf(t / (float)DD + EPSF);
    }
    __syncthreads();
    float sc = sscale;
    float4 gv = ((const float4*)g)[threadIdx.x];
    uint2 u;
    u.x = h2_bits(__floats2half2_rn(xv.x * sc * gv.x, xv.y * sc * gv.y));
    u.y = h2_bits(__floats2half2_rn(xv.z * sc * gv.z, xv.w * sc * gv.w));
    ((uint2*)(out + (size_t)row * DD))[threadIdx.x] = u;
}

// ---------------------------------------------------------------------------
// RoPE on half q,k — half2 vectorized; q scaled by 1/sqrt(dk)=0.125
// ---------------------------------------------------------------------------
#define LOG2_10000_OVER_32 0.41524101186092029f
__global__ void rope_kernel(__half* __restrict__ q, __half* __restrict__ k)
{
    int idx = blockIdx.x * blockDim.x + threadIdx.x;   // < MM*HH*16
    int j2  = idx & 15;
    int h   = (idx >> 4) & (HH - 1);
    int row = idx >> 8;
    int s   = row & (SS - 1);
    int j   = 2 * j2;

    float if0 = exp2f(-(float)j       * LOG2_10000_OVER_32);
    float if1 = exp2f(-(float)(j + 1) * LOG2_10000_OVER_32);
    float sn0, cs0, sn1, cs1;
    sincosf((float)s * if0, &sn0, &cs0);
    sincosf((float)s * if1, &sn1, &cs1);

    size_t base = (size_t)row * DD + h * DKK + j;

    {
        __half2 a = *(__half2*)(q + base);
        __half2 b = *(__half2*)(q + base + 32);
        float a0 = __half2float(a.x), a1 = __half2float(a.y);
        float b0 = __half2float(b.x), b1 = __half2float(b.y);
        *(__half2*)(q + base) = __floats2half2_rn(
            (a0 * cs0 - b0 * sn0) * 0.125f, (a1 * cs1 - b1 * sn1) * 0.125f);
        *(__half2*)(q + base + 32) = __floats2half2_rn(
            (b0 * cs0 + a0 * sn0) * 0.125f, (b1 * cs1 + a1 * sn1) * 0.125f);
    }
    {
        __half2 a = *(__half2*)(k + base);
        __half2 b = *(__half2*)(k + base + 32);
        float a0 = __half2float(a.x), a1 = __half2float(a.y);
        float b0 = __half2float(b.x), b1 = __half2float(b.y);
        *(__half2*)(k + base) = __floats2half2_rn(
            a0 * cs0 - b0 * sn0, a1 * cs1 - b1 * sn1);
        *(__half2*)(k + base + 32) = __floats2half2_rn(
            b0 * cs0 + a0 * sn0, b1 * cs1 + a1 * sn1);
    }
}

// ---------------------------------------------------------------------------
// Flash attention, fp16 m16n8k16 — R11/R13 config + QK^T K-fragments via
// non-trans ldmatrix.x4 (kept from R16; tested as single variable here).
// ---------------------------------------------------------------------------
#define KSH 72
#define VSH 72
#define PSH 72
#define AOFF_K0 0
#define AOFF_K1 (64 * KSH)
#define AOFF_V0 (2 * 64 * KSH)
#define AOFF_V1 (2 * 64 * KSH + 64 * VSH)
#define AOFF_P  (2 * 64 * KSH + 2 * 64 * VSH)
#define ATTN_SMEM ((2 * 64 * KSH + 2 * 64 * VSH + 64 * PSH) * 2)

__global__ void __launch_bounds__(128, 3) attn_mma(
    const __half* __restrict__ q, const __half* __restrict__ k,
    const __half* __restrict__ v, __half* __restrict__ o)
{
    extern __shared__ __half smh[];
    __half* Ks[2] = { smh + AOFF_K0, smh + AOFF_K1 };
    __half* Vs[2] = { smh + AOFF_V0, smh + AOFF_V1 };
    __half* Ps    = smh + AOFF_P;

    const int tid  = threadIdx.x;
    const int lane = tid & 31;
    const int wid  = tid >> 5;
    const int wm   = wid * 16;
    const int tg   = lane >> 2;
    const int tig  = lane & 3;
    const int lm = lane >> 3;
    const int lr = lane & 7;
    const uint32_t vfrag_off =
        (uint32_t)(((lm & 1) * 8 + lr) * VSH + (lm >> 1) * 8) * 2;
    const uint32_t kfrag_off =
        (uint32_t)(((lm & 1) * 8 + lr) * KSH + (lm >> 1) * 8) * 2;

    const int h  = blockIdx.y;
    const int b  = blockIdx.z;
    const int q0 = blockIdx.x * 64;
    const size_t hb = (size_t)h * DKK;

    uint32_t qf[4][4];
    {
        size_t r0 = ((size_t)(b * SS + q0 + wm + tg)) * DD + hb;
        size_t r8 = r0 + (size_t)8 * DD;
        #pragma unroll
        for (int ks = 0; ks < 4; ks++) {
            int c = ks * 16 + 2 * tig;
            qf[ks][0] = *(const uint32_t*)(q + r0 + c);
            qf[ks][1] = *(const uint32_t*)(q + r8 + c);
            qf[ks][2] = *(const uint32_t*)(q + r0 + c + 8);
            qf[ks][3] = *(const uint32_t*)(q + r8 + c + 8);
        }
    }

    float oacc[8][4];
    #pragma unroll
    for (int ni = 0; ni < 8; ni++)
        #pragma unroll
        for (int r = 0; r < 4; r++) oacc[ni][r] = 0.f;
    float m0 = -1e30f, m1 = -1e30f, l0 = 0.f, l1 = 0.f;

    const size_t kvbase = ((size_t)(b * SS)) * DD + hb;

    #define KV_PREFETCH(bf, kt) do {                                          \
        const __half* kg = k + kvbase + (size_t)((kt) * 64) * DD;             \
        const __half* vg = v + kvbase + (size_t)((kt) * 64) * DD;             \
        uint32_t kb = smem_u32(Ks[bf]);                                       \
        uint32_t vb = smem_u32(Vs[bf]);                                       \
        _Pragma("unroll")                                                     \
        for (int i = 0; i < 4; i++) {                                         \
            int e = tid + i * 128;                                            \
            int row = e >> 3, c = e & 7;                                      \
            cp16(kb + (row * KSH + c * 8) * 2, kg + (size_t)row * DD + c * 8);\
            cp16(vb + (row * VSH + c * 8) * 2, vg + (size_t)row * DD + c * 8);\
        }                                                                     \
        asm volatile("cp.async.commit_group;");                               \
    } while (0)

    KV_PREFETCH(0, 0);

    const int NT = SS / 64;
    for (int kt = 0; kt < NT; kt++) {
        int cur = kt & 1;
        asm volatile("cp.async.wait_group 0;");
        __syncthreads();
        if (kt + 1 < NT) KV_PREFETCH(cur ^ 1, kt + 1);

        // ---- S = Q @ K^T (K fragments via ldmatrix.x4) ----
        float sacc[8][4];
        #pragma unroll
        for (int ni = 0; ni < 8; ni++)
            #pragma unroll
            for (int r = 0; r < 4; r++) sacc[ni][r] = 0.f;

        uint32_t kmBase = smem_u32(Ks[cur]) + kfrag_off;
        #pragma unroll
        for (int ks = 0; ks < 4; ks++) {
            #pragma unroll
            for (int g = 0; g < 4; g++) {
                uint32_t r0, r1, r2, r3;
                LDSM_X4(r0, r1, r2, r3,
                        kmBase + (uint32_t)(g * 16 * KSH + ks * 16) * 2);
                uint32_t bA[2] = { r0, r2 };
                uint32_t bB[2] = { r1, r3 };
                mma_f16(sacc[2 * g    ], qf[ks], bA);
                mma_f16(sacc[2 * g + 1], qf[ks], bB);
            }
        }

        // ---- online softmax ----
        float rmax0 = -1e30f, rmax1 = -1e30f;
        #pragma unroll
        for (int ni = 0; ni < 8; ni++) {
            rmax0 = fmaxf(rmax0, fmaxf(sacc[ni][0], sacc[ni][1]));
            rmax1 = fmaxf(rmax1, fmaxf(sacc[ni][2], sacc[ni][3]));
        }
        #pragma unroll
        for (int d = 1; d < 4; d <<= 1) {
            rmax0 = fmaxf(rmax0, __shfl_xor_sync(0xFFFFFFFFu, rmax0, d));
            rmax1 = fmaxf(rmax1, __shfl_xor_sync(0xFFFFFFFFu, rmax1, d));
        }
        float nm0 = fmaxf(m0, rmax0);
        float nm1 = fmaxf(m1, rmax1);
        float corr0 = __expf(m0 - nm0);
        float corr1 = __expf(m1 - nm1);

        float rsum0 = 0.f, rsum1 = 0.f;
        #pragma unroll
        for (int ni = 0; ni < 8; ni++) {
            float p0 = __expf(sacc[ni][0] - nm0);
            float p1 = __expf(sacc[ni][1] - nm0);
            float p2 = __expf(sacc[ni][2] - nm1);
            float p3 = __expf(sacc[ni][3] - nm1);
            rsum0 += p0 + p1;
            rsum1 += p2 + p3;
            *(__half2*)(Ps + (wm + tg    ) * PSH + ni * 8 + 2 * tig) =
                __floats2half2_rn(p0, p1);
            *(__half2*)(Ps + (wm + tg + 8) * PSH + ni * 8 + 2 * tig) =
                __floats2half2_rn(p2, p3);
        }
        #pragma unroll
        for (int d = 1; d < 4; d <<= 1) {
            rsum0 += __shfl_xor_sync(0xFFFFFFFFu, rsum0, d);
            rsum1 += __shfl_xor_sync(0xFFFFFFFFu, rsum1, d);
        }
        l0 = l0 * corr0 + rsum0;
        l1 = l1 * corr1 + rsum1;
        m0 = nm0; m1 = nm1;

        #pragma unroll
        for (int ni = 0; ni < 8; ni++) {
            oacc[ni][0] *= corr0; oacc[ni][1] *= corr0;
            oacc[ni][2] *= corr1; oacc[ni][3] *= corr1;
        }

        __syncwarp();

        // ---- O += P @ V ----
        uint32_t vmBase = smem_u32(Vs[cur]) + vfrag_off;
        #pragma unroll
        for (int ks = 0; ks < 4; ks++) {
            uint32_t af[4];
            const __half* pr = Ps + (wm + tg) * PSH + ks * 16 + 2 * tig;
            af[0] = *(const uint32_t*)(pr);
            af[1] = *(const uint32_t*)(pr + 8 * PSH);
            af[2] = *(const uint32_t*)(pr + 8);
            af[3] = *(const uint32_t*)(pr + 8 * PSH + 8);
            #pragma unroll
            for (int nip = 0; nip < 4; nip++) {
                uint32_t b0a, b1a, b0b, b1b;
                LDSM_X4T(b0a, b1a, b0b, b1b,
                         vmBase + (uint32_t)(ks * 16 * VSH + nip * 16) * 2);
                uint32_t bA[2] = { b0a, b1a };
                uint32_t bB[2] = { b0b, b1b };
                mma_f16(oacc[2 * nip    ], af, bA);
                mma_f16(oacc[2 * nip + 1], af, bB);
            }
        }
        __syncwarp();
    }

    float inv0 = 1.f / l0;
    float inv1 = 1.f / l1;
    size_t r0 = ((size_t)(b * SS + q0 + wm + tg)) * DD + hb;
    size_t r8 = r0 + (size_t)8 * DD;
    #pragma unroll
    for (int ni = 0; ni < 8; ni++) {
        int c = ni * 8 + 2 * tig;
        *(__half2*)(o + r0 + c) =
            __floats2half2_rn(oacc[ni][0] * inv0, oacc[ni][1] * inv0);
        *(__half2*)(o + r8 + c) =
            __floats2half2_rn(oacc[ni][2] * inv1, oacc[ni][3] * inv1);
    }
    #undef KV_PREFETCH
}

// ---------------------------------------------------------------------------
// Host orchestration
// ---------------------------------------------------------------------------
extern "C" void kernel_launch(void* const* d_in, const int* in_sizes, int n_in,
                              void* d_out, int out_size)
{
    (void)in_sizes; (void)n_in; (void)out_size;

    const float* x  = (const float*)d_in[0];
    const float* wq = (const float*)d_in[1];
    const float* bq = (const float*)d_in[2];
    const float* wk = (const float*)d_in[3];
    const float* bk = (const float*)d_in[4];
    const float* wv = (const float*)d_in[5];
    const float* bv = (const float*)d_in[6];
    const float* wo = (const float*)d_in[7];
    const float* bo = (const float*)d_in[8];
    const float* w1 = (const float*)d_in[9];
    const float* b1 = (const float*)d_in[10];
    const float* w2 = (const float*)d_in[11];
    const float* b2 = (const float*)d_in[12];
    const float* g1 = (const float*)d_in[13];
    const float* g2 = (const float*)d_in[14];
    float* out = (float*)d_out;

    __half *ph, *pq, *pk, *pv, *po, *ph2, *pff;
    float  *px2;
    uint32_t *ppwq, *ppwk, *ppwv, *ppwo, *ppw1, *ppw2;
    cudaGetSymbolAddress((void**)&ph,  g_h);
    cudaGetSymbolAddress((void**)&pq,  g_q);
    cudaGetSymbolAddress((void**)&pk,  g_k);
    cudaGetSymbolAddress((void**)&pv,  g_v);
    cudaGetSymbolAddress((void**)&po,  g_o);
    cudaGetSymbolAddress((void**)&px2, g_x2);
    cudaGetSymbolAddress((void**)&ph2, g_h2);
    cudaGetSymbolAddress((void**)&pff, g_ff);
    cudaGetSymbolAddress((void**)&ppwq, g_pwq);
    cudaGetSymbolAddress((void**)&ppwk, g_pwk);
    cudaGetSymbolAddress((void**)&ppwv, g_pwv);
    cudaGetSymbolAddress((void**)&ppwo, g_pwo);
    cudaGetSymbolAddress((void**)&ppw1, g_pw1);
    cudaGetSymbolAddress((void**)&ppw2, g_pw2);

    cudaFuncSetAttribute(attn_mma,
        cudaFuncAttributeMaxDynamicSharedMemorySize, ATTN_SMEM);
    cudaFuncSetAttribute(gemm_h,
        cudaFuncAttributeMaxDynamicSharedMemorySize, GEMM_SMEM);
    cudaFuncSetAttribute(gemm_qkv,
        cudaFuncAttributeMaxDynamicSharedMemorySize, GEMM_SMEM);

    dim3 gD(DD / BN,   MM / BM);   // (8, 32)
    dim3 gF(DFFF / BN, MM / BM);   // (32, 32)

    // 1) pack all weights in one launch
    pack_all_kernel<<<PACK_BLOCKS, 256>>>(
        wq, wk, wv, wo, w1, w2, ppwq, ppwk, ppwv, ppwo, ppw1, ppw2);

    // 2) h = rmsnorm(x, g1) -> half
    rmsnorm_h_kernel<<<MM, 256>>>(x, g1, ph);

    // 3) fused QKV projections -> half q,k,v
    gemm_qkv<<<dim3(24, MM / BM), 256, GEMM_SMEM>>>(
        ph, ppwq, ppwk, ppwv, bq, bk, bv, pq, pk, pv);

    // 4) RoPE on half q,k
    rope_kernel<<<(MM * HH * 16) / 256, 256>>>(pq, pk);

    // 5) attention (fp16, 64-query CTAs, 3 CTA/SM) -> o half
    attn_mma<<<dim3(SS / 64, HH, BB), 128, ATTN_SMEM>>>(pq, pk, pv, po);

    // 6) x2 = x + o @ wo + bo   (fp32 out)
    gemm_h<<<gD, 256, GEMM_SMEM>>>(po, ppwo, bo, x, px2, DD, DD, 2, 0);

    // 7) h2 = rmsnorm(x2, g2) -> half
    rmsnorm_h_kernel<<<MM, 256>>>(px2, g2, ph2);

    // 8) ff = relu(h2 @ w1 + b1) -> half
    gemm_h<<<gF, 256, GEMM_SMEM>>>(ph2, ppw1, b1, nullptr, pff, DFFF, DD, 1, 2);

    // 9) out = x2 + ff @ w2 + b2   (fp32 out)
    gemm_h<<<gD, 256, GEMM_SMEM>>>(pff, ppw2, b2, px2, out, DD, DFFF, 2, 0);
}